// round 1
// baseline (speedup 1.0000x reference)
#include <cuda_runtime.h>
#include <cuda_bf16.h>
#include <cstdint>

// Problem constants
constexpr int Bq = 2, Tq = 2048, Cq = 1024, Hq = 16, Dq = 64;
constexpr int Mrows = Bq * Tq;      // 4096
constexpr int N_QKV = 3 * Cq;       // 3072

// Scratch (device globals — no allocation allowed)
__device__ float g_q[Bq * Hq * Tq * Dq];   // [B,H,T,D]
__device__ float g_k[Bq * Hq * Tq * Dq];
__device__ float g_v[Bq * Hq * Tq * Dq];
__device__ float g_y[Bq * Tq * Cq];        // [B,T,C]

// ---------------------------------------------------------------------------
// SGEMM 128x128x16, 256 threads, 8x8 per thread
// ---------------------------------------------------------------------------
constexpr int BM = 128, BN = 128, BK = 16, TM = 8, TN = 8;

// QKV GEMM: X[M,K] @ W[K,3C], epilogue scatters into [B,H,T,D] q/k/v
__global__ __launch_bounds__(256) void gemm_qkv(const float* __restrict__ A,
                                                const float* __restrict__ W) {
    const int K = Cq, N = N_QKV;
    __shared__ float As[BK][BM];
    __shared__ float Bs[BK][BN];
    const int tid = threadIdx.x;
    const int m0 = blockIdx.y * BM, n0 = blockIdx.x * BN;
    const int tx = tid & 15, ty = tid >> 4;

    float acc[TM][TN];
#pragma unroll
    for (int i = 0; i < TM; i++)
#pragma unroll
        for (int j = 0; j < TN; j++) acc[i][j] = 0.f;

    const int ar = tid >> 2;          // 0..63
    const int ac = (tid & 3) * 4;     // 0,4,8,12
    const int br = tid >> 5;          // 0..7
    const int bc = (tid & 31) * 4;    // 0..124

    for (int k0 = 0; k0 < K; k0 += BK) {
#pragma unroll
        for (int s = 0; s < 2; s++) {
            int r = ar + s * 64;
            float4 v = *(const float4*)(A + (size_t)(m0 + r) * K + k0 + ac);
            As[ac + 0][r] = v.x; As[ac + 1][r] = v.y;
            As[ac + 2][r] = v.z; As[ac + 3][r] = v.w;
        }
#pragma unroll
        for (int s = 0; s < 2; s++) {
            int r = br + s * 8;
            *(float4*)&Bs[r][bc] = *(const float4*)(W + (size_t)(k0 + r) * N + n0 + bc);
        }
        __syncthreads();
#pragma unroll
        for (int kt = 0; kt < BK; kt++) {
            float a[TM], b[TN];
#pragma unroll
            for (int i = 0; i < TM; i++) a[i] = As[kt][ty * TM + i];
#pragma unroll
            for (int j = 0; j < TN; j++) b[j] = Bs[kt][tx * TN + j];
#pragma unroll
            for (int i = 0; i < TM; i++)
#pragma unroll
                for (int j = 0; j < TN; j++) acc[i][j] += a[i] * b[j];
        }
        __syncthreads();
    }

    // scatter epilogue: n -> (which, h, d); m -> (b, t); dst[(b*H+h)*T + t][d]
#pragma unroll
    for (int i = 0; i < TM; i++) {
        int m = m0 + ty * TM + i;
        int bb = m >> 11;             // /2048
        int t = m & (Tq - 1);
#pragma unroll
        for (int j = 0; j < TN; j++) {
            int n = n0 + tx * TN + j;
            int which = n >> 10;      // /1024
            int c = n & (Cq - 1);
            int h = c >> 6, d = c & 63;
            float* dst = (which == 0) ? g_q : (which == 1) ? g_k : g_v;
            dst[(((bb * Hq) + h) * Tq + t) * Dq + d] = acc[i][j];
        }
    }
}

// Output projection: Y[M,K] @ Wo[K,C] + bo -> out [B,T,C]
__global__ __launch_bounds__(256) void gemm_proj(const float* __restrict__ W,
                                                 const float* __restrict__ bias,
                                                 float* __restrict__ out) {
    const int K = Cq, N = Cq;
    const float* A = g_y;
    __shared__ float As[BK][BM];
    __shared__ float Bs[BK][BN];
    const int tid = threadIdx.x;
    const int m0 = blockIdx.y * BM, n0 = blockIdx.x * BN;
    const int tx = tid & 15, ty = tid >> 4;

    float acc[TM][TN];
#pragma unroll
    for (int i = 0; i < TM; i++)
#pragma unroll
        for (int j = 0; j < TN; j++) acc[i][j] = 0.f;

    const int ar = tid >> 2;
    const int ac = (tid & 3) * 4;
    const int br = tid >> 5;
    const int bc = (tid & 31) * 4;

    for (int k0 = 0; k0 < K; k0 += BK) {
#pragma unroll
        for (int s = 0; s < 2; s++) {
            int r = ar + s * 64;
            float4 v = *(const float4*)(A + (size_t)(m0 + r) * K + k0 + ac);
            As[ac + 0][r] = v.x; As[ac + 1][r] = v.y;
            As[ac + 2][r] = v.z; As[ac + 3][r] = v.w;
        }
#pragma unroll
        for (int s = 0; s < 2; s++) {
            int r = br + s * 8;
            *(float4*)&Bs[r][bc] = *(const float4*)(W + (size_t)(k0 + r) * N + n0 + bc);
        }
        __syncthreads();
#pragma unroll
        for (int kt = 0; kt < BK; kt++) {
            float a[TM], b[TN];
#pragma unroll
            for (int i = 0; i < TM; i++) a[i] = As[kt][ty * TM + i];
#pragma unroll
            for (int j = 0; j < TN; j++) b[j] = Bs[kt][tx * TN + j];
#pragma unroll
            for (int i = 0; i < TM; i++)
#pragma unroll
                for (int j = 0; j < TN; j++) acc[i][j] += a[i] * b[j];
        }
        __syncthreads();
    }

#pragma unroll
    for (int i = 0; i < TM; i++) {
        int m = m0 + ty * TM + i;
#pragma unroll
        for (int j = 0; j < TN; j++) {
            int n = n0 + tx * TN + j;
            out[(size_t)m * N + n] = acc[i][j] + __ldg(&bias[n]);
        }
    }
}

// ---------------------------------------------------------------------------
// Flash attention (causal), fp32. 128 query rows / block, 1 row / thread.
// K/V tiles of 32 rows staged in shared; broadcast reads.
// ---------------------------------------------------------------------------
constexpr int AT_BM = 128;   // queries per block
constexpr int AT_BN = 32;    // keys per tile

__global__ __launch_bounds__(128) void flash_attn() {
    const int bh = blockIdx.y;            // b*H + h
    const int q0 = blockIdx.x * AT_BM;
    const int t = threadIdx.x;
    const int qrow = q0 + t;
    const float scale = 0.125f;           // 1/sqrt(64)

    __shared__ float Ks[AT_BN][Dq];
    __shared__ float Vs[AT_BN][Dq];

    // Q row into registers
    float q[Dq];
    {
        const float4* qp = (const float4*)(g_q + ((size_t)bh * Tq + qrow) * Dq);
#pragma unroll
        for (int i = 0; i < Dq / 4; i++) {
            float4 v = qp[i];
            q[4 * i + 0] = v.x; q[4 * i + 1] = v.y;
            q[4 * i + 2] = v.z; q[4 * i + 3] = v.w;
        }
    }

    float O[Dq];
#pragma unroll
    for (int d = 0; d < Dq; d++) O[d] = 0.f;
    float m = -1e30f, l = 0.f;

    const int kend = q0 + AT_BM;          // causal: keys < kend
    for (int j0 = 0; j0 < kend; j0 += AT_BN) {
        // cooperative load of K/V tiles (2048 floats each = 512 float4)
        {
            const float4* ksrc = (const float4*)(g_k + ((size_t)bh * Tq + j0) * Dq);
            const float4* vsrc = (const float4*)(g_v + ((size_t)bh * Tq + j0) * Dq);
            float4* kdst = (float4*)&Ks[0][0];
            float4* vdst = (float4*)&Vs[0][0];
#pragma unroll
            for (int r = 0; r < 4; r++) {
                kdst[t + 128 * r] = ksrc[t + 128 * r];
                vdst[t + 128 * r] = vsrc[t + 128 * r];
            }
        }
        __syncthreads();

        float s[AT_BN];
#pragma unroll
        for (int j = 0; j < AT_BN; j++) {
            const float4* kr = (const float4*)Ks[j];
            float acc = 0.f;
#pragma unroll
            for (int i = 0; i < Dq / 4; i++) {
                float4 kv = kr[i];
                acc += q[4 * i + 0] * kv.x + q[4 * i + 1] * kv.y
                     + q[4 * i + 2] * kv.z + q[4 * i + 3] * kv.w;
            }
            s[j] = (j0 + j <= qrow) ? acc * scale : -1e30f;
        }

        float mt = m;
#pragma unroll
        for (int j = 0; j < AT_BN; j++) mt = fmaxf(mt, s[j]);

        float corr = __expf(m - mt);
        l *= corr;
#pragma unroll
        for (int d = 0; d < Dq; d++) O[d] *= corr;

#pragma unroll
        for (int j = 0; j < AT_BN; j++) {
            float p = __expf(s[j] - mt);
            l += p;
            const float4* vr = (const float4*)Vs[j];
#pragma unroll
            for (int i = 0; i < Dq / 4; i++) {
                float4 vv = vr[i];
                O[4 * i + 0] += p * vv.x; O[4 * i + 1] += p * vv.y;
                O[4 * i + 2] += p * vv.z; O[4 * i + 3] += p * vv.w;
            }
        }
        m = mt;
        __syncthreads();
    }

    const float inv = 1.0f / l;
    const int bb = bh >> 4, h = bh & 15;
    float* yo = g_y + ((size_t)(bb * Tq + qrow)) * Cq + h * Dq;
    float4* yo4 = (float4*)yo;
#pragma unroll
    for (int i = 0; i < Dq / 4; i++) {
        float4 v;
        v.x = O[4 * i + 0] * inv; v.y = O[4 * i + 1] * inv;
        v.z = O[4 * i + 2] * inv; v.w = O[4 * i + 3] * inv;
        yo4[i] = v;
    }
}

// ---------------------------------------------------------------------------
extern "C" void kernel_launch(void* const* d_in, const int* in_sizes, int n_in,
                              void* d_out, int out_size) {
    const float* x    = (const float*)d_in[0];   // [B,T,C]
    const float* Wqkv = (const float*)d_in[1];   // [C,3C]
    const float* Wo   = (const float*)d_in[2];   // [C,C]
    const float* bo   = (const float*)d_in[3];   // [C]
    float* out = (float*)d_out;                  // [B,T,C]

    dim3 g1(N_QKV / BN, Mrows / BM);             // 24 x 32
    gemm_qkv<<<g1, 256>>>(x, Wqkv);

    dim3 g2(Tq / AT_BM, Bq * Hq);                // 16 x 32
    flash_attn<<<g2, 128>>>();

    dim3 g3(Cq / BN, Mrows / BM);                // 8 x 32
    gemm_proj<<<g3, 256>>>(Wo, bo, out);
}

// round 3
// speedup vs baseline: 3.4062x; 3.4062x over previous
#include <cuda_runtime.h>
#include <cuda_bf16.h>
#include <cstdint>

// ---------------------------------------------------------------------------
// Problem constants
// ---------------------------------------------------------------------------
constexpr int Bq = 2, Tq = 2048, Cq = 1024, Hq = 16, Dq = 64;
constexpr int Mrows = Bq * Tq;      // 4096
constexpr int N_QKV = 3 * Cq;       // 3072

// Scratch (device globals — no allocation allowed)
__device__ float g_q[Bq * Hq * Tq * Dq];   // [B,H,T,D]
__device__ float g_k[Bq * Hq * Tq * Dq];
__device__ float g_v[Bq * Hq * Tq * Dq];
__device__ float g_y[Bq * Tq * Cq];        // [B,T,C]
__device__ float g_wqkv_t[N_QKV * Cq];     // [3C, C]  (Wqkv^T, K-major)
__device__ float g_wo_t[Cq * Cq];          // [C, C]   (Wo^T, K-major)

// ---------------------------------------------------------------------------
// Helpers
// ---------------------------------------------------------------------------
__device__ __forceinline__ uint32_t f2tf(float x) {
    uint32_t r;
    asm("cvt.rna.tf32.f32 %0, %1;" : "=r"(r) : "f"(x));
    return r;
}

// mma.sync m16n8k8 tf32 (generic PTX, works on sm_103 target)
__device__ __forceinline__ void mma8(float* d, const uint32_t* a, const uint32_t* b) {
    asm volatile(
        "mma.sync.aligned.m16n8k8.row.col.f32.tf32.tf32.f32 "
        "{%0,%1,%2,%3}, {%4,%5,%6,%7}, {%8,%9}, {%0,%1,%2,%3};\n"
        : "+f"(d[0]), "+f"(d[1]), "+f"(d[2]), "+f"(d[3])
        : "r"(a[0]), "r"(a[1]), "r"(a[2]), "r"(a[3]), "r"(b[0]), "r"(b[1]));
}

// ---------------------------------------------------------------------------
// Transpose: src [R, Cn] -> dst [Cn, R]
// ---------------------------------------------------------------------------
__global__ __launch_bounds__(256) void transpose_k(const float* __restrict__ src,
                                                   float* __restrict__ dst,
                                                   int R, int Cn) {
    __shared__ float tile[32][33];
    int c0 = blockIdx.x * 32, r0 = blockIdx.y * 32;
    int x = threadIdx.x, y = threadIdx.y;   // 32 x 8
#pragma unroll
    for (int i = 0; i < 32; i += 8)
        tile[y + i][x] = src[(size_t)(r0 + y + i) * Cn + c0 + x];
    __syncthreads();
#pragma unroll
    for (int i = 0; i < 32; i += 8)
        dst[(size_t)(c0 + y + i) * R + r0 + x] = tile[x][y + i];
}

// ---------------------------------------------------------------------------
// tf32 mma.sync GEMM: D[M,N] = A[M,K] @ BT[N,K]^T
// CTA 128x128, BK=32, 8 warps (2x4), warp tile 64x32, double-buffered SMEM.
// mode 0: scatter into g_q/g_k/g_v ([B,H,T,D]); mode 1: out = D + bias
// ---------------------------------------------------------------------------
constexpr int GST = 36;                       // smem row stride (floats), conflict-free
constexpr int GEMM_STAGE = 2 * 128 * GST;     // floats per stage (A then B)
constexpr int GEMM_SMEM = 2 * GEMM_STAGE * 4; // 73728 bytes

__global__ void __launch_bounds__(256, 2) gemm_mma(const float* __restrict__ A,
                                                   const float* __restrict__ BT,
                                                   int Ktot, int mode,
                                                   const float* __restrict__ bias,
                                                   float* __restrict__ outp) {
    extern __shared__ float sm[];
    const int tid = threadIdx.x, lane = tid & 31, wid = tid >> 5;
    const int wm = wid >> 2, wn = wid & 3;
    const int m0 = blockIdx.y * 128, n0 = blockIdx.x * 128;

    const int lr = tid >> 1, lc = (tid & 1) * 16;
    const float* gA = A  + (size_t)(m0 + lr) * Ktot + lc;
    const float* gB = BT + (size_t)(n0 + lr) * Ktot + lc;

    float d[4][4][4];
#pragma unroll
    for (int mi = 0; mi < 4; mi++)
#pragma unroll
        for (int ni = 0; ni < 4; ni++)
#pragma unroll
            for (int e = 0; e < 4; e++) d[mi][ni][e] = 0.f;

    float4 ra[4], rb[4];
    const int nc = Ktot / 32;

    // prologue: chunk 0
    {
#pragma unroll
        for (int j = 0; j < 4; j++) {
            ra[j] = *(const float4*)(gA + j * 4);
            rb[j] = *(const float4*)(gB + j * 4);
        }
        float* p = sm + lr * GST + lc;
#pragma unroll
        for (int j = 0; j < 4; j++) {
            float4 t = ra[j];
            t.x = __uint_as_float(f2tf(t.x)); t.y = __uint_as_float(f2tf(t.y));
            t.z = __uint_as_float(f2tf(t.z)); t.w = __uint_as_float(f2tf(t.w));
            *(float4*)(p + j * 4) = t;
            float4 u = rb[j];
            u.x = __uint_as_float(f2tf(u.x)); u.y = __uint_as_float(f2tf(u.y));
            u.z = __uint_as_float(f2tf(u.z)); u.w = __uint_as_float(f2tf(u.w));
            *(float4*)(p + 128 * GST + j * 4) = u;
        }
    }
    __syncthreads();

    for (int c = 0; c < nc; c++) {
        if (c + 1 < nc) {
            const float* pa = gA + (c + 1) * 32;
            const float* pb = gB + (c + 1) * 32;
#pragma unroll
            for (int j = 0; j < 4; j++) {
                ra[j] = *(const float4*)(pa + j * 4);
                rb[j] = *(const float4*)(pb + j * 4);
            }
        }
        // compute on stage c&1
        const float* cA = sm + (c & 1) * GEMM_STAGE;
        const float* cB = cA + 128 * GST;
#pragma unroll
        for (int ks = 0; ks < 4; ks++) {
            const int kc = ks * 8 + (lane & 3);
            uint32_t a[4][4], b[4][2];
#pragma unroll
            for (int mi = 0; mi < 4; mi++) {
                int r = wm * 64 + mi * 16 + (lane >> 2);
                a[mi][0] = __float_as_uint(cA[r * GST + kc]);
                a[mi][1] = __float_as_uint(cA[(r + 8) * GST + kc]);
                a[mi][2] = __float_as_uint(cA[r * GST + kc + 4]);
                a[mi][3] = __float_as_uint(cA[(r + 8) * GST + kc + 4]);
            }
#pragma unroll
            for (int ni = 0; ni < 4; ni++) {
                int cn = wn * 32 + ni * 8 + (lane >> 2);
                b[ni][0] = __float_as_uint(cB[cn * GST + kc]);
                b[ni][1] = __float_as_uint(cB[cn * GST + kc + 4]);
            }
#pragma unroll
            for (int mi = 0; mi < 4; mi++)
#pragma unroll
                for (int ni = 0; ni < 4; ni++) mma8(d[mi][ni], a[mi], b[ni]);
        }
        if (c + 1 < nc) {
            float* p = sm + ((c + 1) & 1) * GEMM_STAGE + lr * GST + lc;
#pragma unroll
            for (int j = 0; j < 4; j++) {
                float4 t = ra[j];
                t.x = __uint_as_float(f2tf(t.x)); t.y = __uint_as_float(f2tf(t.y));
                t.z = __uint_as_float(f2tf(t.z)); t.w = __uint_as_float(f2tf(t.w));
                *(float4*)(p + j * 4) = t;
                float4 u = rb[j];
                u.x = __uint_as_float(f2tf(u.x)); u.y = __uint_as_float(f2tf(u.y));
                u.z = __uint_as_float(f2tf(u.z)); u.w = __uint_as_float(f2tf(u.w));
                *(float4*)(p + 128 * GST + j * 4) = u;
            }
        }
        __syncthreads();
    }

    // epilogue
#pragma unroll
    for (int mi = 0; mi < 4; mi++) {
#pragma unroll
        for (int half = 0; half < 2; half++) {
            int m = m0 + wm * 64 + mi * 16 + (lane >> 2) + half * 8;
            int bb = m >> 11, t = m & (Tq - 1);
#pragma unroll
            for (int ni = 0; ni < 4; ni++) {
                int n = n0 + wn * 32 + ni * 8 + 2 * (lane & 3);
                float2 v;
                v.x = d[mi][ni][half * 2 + 0];
                v.y = d[mi][ni][half * 2 + 1];
                if (mode == 0) {
                    int which = n >> 10, cc = n & (Cq - 1);
                    int hh = cc >> 6, dd = cc & 63;
                    float* dst = (which == 0) ? g_q : (which == 1) ? g_k : g_v;
                    *(float2*)(dst + (((size_t)(bb * Hq + hh) * Tq + t) * Dq + dd)) = v;
                } else {
                    v.x += __ldg(bias + n);
                    v.y += __ldg(bias + n + 1);
                    *(float2*)(outp + (size_t)m * Cq + n) = v;
                }
            }
        }
    }
}

// ---------------------------------------------------------------------------
// Warp-MMA flash attention (causal). 128 q-rows/CTA, 8 warps x 16 rows,
// 64-key tiles. S and PV on tf32 mma.sync; softmax in registers.
// ---------------------------------------------------------------------------
constexpr int FST = 68;                    // smem row stride (floats)
constexpr int F_SK = 0;                    // K tile   [64][FST]
constexpr int F_SV = 64 * FST;             // V^T tile [64][FST]  (sVt[d][key])
constexpr int F_SP = 2 * 64 * FST;         // P tile   [128][FST]
constexpr int FLASH_SMEM = (2 * 64 * FST + 128 * FST) * 4;  // 69632 bytes

__global__ void __launch_bounds__(256, 2) flash_mma() {
    extern __shared__ float sm[];
    const int tid = threadIdx.x, lane = tid & 31, wid = tid >> 5;
    const int bh = blockIdx.y, q0 = blockIdx.x * 128;
    const int bb = bh >> 4, h = bh & 15;
    const float scale = 0.125f;

    // Q fragments in registers (scale folded in)
    uint32_t qa[8][4];
    {
        const float* r0p = g_q + ((size_t)bh * Tq + q0 + wid * 16 + (lane >> 2)) * Dq;
        const float* r1p = r0p + 8 * Dq;
#pragma unroll
        for (int ks = 0; ks < 8; ks++) {
            int c = ks * 8 + (lane & 3);
            qa[ks][0] = f2tf(r0p[c] * scale);
            qa[ks][1] = f2tf(r1p[c] * scale);
            qa[ks][2] = f2tf(r0p[c + 4] * scale);
            qa[ks][3] = f2tf(r1p[c + 4] * scale);
        }
    }

    float o[8][4];
#pragma unroll
    for (int ni = 0; ni < 8; ni++)
#pragma unroll
        for (int e = 0; e < 4; e++) o[ni][e] = 0.f;
    float m_a = -1e30f, m_b = -1e30f, l_a = 0.f, l_b = 0.f;
    const int row_a = q0 + wid * 16 + (lane >> 2);
    const int row_b = row_a + 8;

    float* Pr_a = sm + F_SP + (wid * 16 + (lane >> 2)) * FST;
    float* Pr_b = Pr_a + 8 * FST;

    for (int j0 = 0; j0 < q0 + 128; j0 += 64) {
        __syncthreads();
        // stage K tile and transposed V tile (tf32-converted)
        {
            int key = tid >> 2, db = (tid & 3) * 16;
            const float* kp = g_k + ((size_t)bh * Tq + j0 + key) * Dq + db;
            const float* vp = g_v + ((size_t)bh * Tq + j0 + key) * Dq + db;
            float* skrow = sm + F_SK + key * FST + db;
#pragma unroll
            for (int j = 0; j < 4; j++) {
                float4 kv = *(const float4*)(kp + j * 4);
                kv.x = __uint_as_float(f2tf(kv.x)); kv.y = __uint_as_float(f2tf(kv.y));
                kv.z = __uint_as_float(f2tf(kv.z)); kv.w = __uint_as_float(f2tf(kv.w));
                *(float4*)(skrow + j * 4) = kv;
                float4 vv = *(const float4*)(vp + j * 4);
                sm[F_SV + (db + j * 4 + 0) * FST + key] = __uint_as_float(f2tf(vv.x));
                sm[F_SV + (db + j * 4 + 1) * FST + key] = __uint_as_float(f2tf(vv.y));
                sm[F_SV + (db + j * 4 + 2) * FST + key] = __uint_as_float(f2tf(vv.z));
                sm[F_SV + (db + j * 4 + 3) * FST + key] = __uint_as_float(f2tf(vv.w));
            }
        }
        __syncthreads();

        // S = Q K^T  (16 rows x 64 keys per warp)
        float s[8][4];
#pragma unroll
        for (int ni = 0; ni < 8; ni++)
#pragma unroll
            for (int e = 0; e < 4; e++) s[ni][e] = 0.f;
#pragma unroll
        for (int ks = 0; ks < 8; ks++) {
            const int kc = ks * 8 + (lane & 3);
#pragma unroll
            for (int ni = 0; ni < 8; ni++) {
                uint32_t b[2];
                const float* kr = sm + F_SK + (ni * 8 + (lane >> 2)) * FST;
                b[0] = __float_as_uint(kr[kc]);
                b[1] = __float_as_uint(kr[kc + 4]);
                mma8(s[ni], qa[ks], b);
            }
        }

        // causal mask (diagonal tiles only)
        if (j0 >= q0) {
#pragma unroll
            for (int ni = 0; ni < 8; ni++) {
                int c0 = j0 + ni * 8 + 2 * (lane & 3);
                if (c0     > row_a) s[ni][0] = -1e30f;
                if (c0 + 1 > row_a) s[ni][1] = -1e30f;
                if (c0     > row_b) s[ni][2] = -1e30f;
                if (c0 + 1 > row_b) s[ni][3] = -1e30f;
            }
        }

        // online softmax
        float ma = -1e30f, mb = -1e30f;
#pragma unroll
        for (int ni = 0; ni < 8; ni++) {
            ma = fmaxf(ma, fmaxf(s[ni][0], s[ni][1]));
            mb = fmaxf(mb, fmaxf(s[ni][2], s[ni][3]));
        }
        ma = fmaxf(ma, __shfl_xor_sync(0xffffffffu, ma, 1));
        ma = fmaxf(ma, __shfl_xor_sync(0xffffffffu, ma, 2));
        mb = fmaxf(mb, __shfl_xor_sync(0xffffffffu, mb, 1));
        mb = fmaxf(mb, __shfl_xor_sync(0xffffffffu, mb, 2));
        float mna = fmaxf(m_a, ma), mnb = fmaxf(m_b, mb);
        float ca = __expf(m_a - mna), cb = __expf(m_b - mnb);
        m_a = mna; m_b = mnb;
        float sa = 0.f, sb = 0.f;
#pragma unroll
        for (int ni = 0; ni < 8; ni++) {
            s[ni][0] = __expf(s[ni][0] - m_a);
            s[ni][1] = __expf(s[ni][1] - m_a);
            sa += s[ni][0] + s[ni][1];
            s[ni][2] = __expf(s[ni][2] - m_b);
            s[ni][3] = __expf(s[ni][3] - m_b);
            sb += s[ni][2] + s[ni][3];
        }
        sa += __shfl_xor_sync(0xffffffffu, sa, 1);
        sa += __shfl_xor_sync(0xffffffffu, sa, 2);
        sb += __shfl_xor_sync(0xffffffffu, sb, 1);
        sb += __shfl_xor_sync(0xffffffffu, sb, 2);
        l_a = l_a * ca + sa;
        l_b = l_b * cb + sb;
#pragma unroll
        for (int ni = 0; ni < 8; ni++) {
            o[ni][0] *= ca; o[ni][1] *= ca;
            o[ni][2] *= cb; o[ni][3] *= cb;
        }

        // write P to smem (tf32) for re-fragmenting as A operand
#pragma unroll
        for (int ni = 0; ni < 8; ni++) {
            int c = ni * 8 + 2 * (lane & 3);
            float2 pv;
            pv.x = __uint_as_float(f2tf(s[ni][0]));
            pv.y = __uint_as_float(f2tf(s[ni][1]));
            *(float2*)(Pr_a + c) = pv;
            pv.x = __uint_as_float(f2tf(s[ni][2]));
            pv.y = __uint_as_float(f2tf(s[ni][3]));
            *(float2*)(Pr_b + c) = pv;
        }
        __syncwarp();

        // O += P V
#pragma unroll
        for (int ks = 0; ks < 8; ks++) {
            const int kc = ks * 8 + (lane & 3);
            uint32_t pa[4];
            pa[0] = __float_as_uint(Pr_a[kc]);
            pa[1] = __float_as_uint(Pr_b[kc]);
            pa[2] = __float_as_uint(Pr_a[kc + 4]);
            pa[3] = __float_as_uint(Pr_b[kc + 4]);
#pragma unroll
            for (int ni = 0; ni < 8; ni++) {
                uint32_t vb[2];
                const float* vr = sm + F_SV + (ni * 8 + (lane >> 2)) * FST;
                vb[0] = __float_as_uint(vr[kc]);
                vb[1] = __float_as_uint(vr[kc + 4]);
                mma8(o[ni], pa, vb);
            }
        }
    }

    // normalize + write to g_y [B,T,C]
    const float ia = 1.f / l_a, ib = 1.f / l_b;
    float* ya = g_y + ((size_t)(bb * Tq + row_a)) * Cq + h * Dq;
    float* yb = g_y + ((size_t)(bb * Tq + row_b)) * Cq + h * Dq;
#pragma unroll
    for (int ni = 0; ni < 8; ni++) {
        int c = ni * 8 + 2 * (lane & 3);
        float2 v;
        v.x = o[ni][0] * ia; v.y = o[ni][1] * ia;
        *(float2*)(ya + c) = v;
        v.x = o[ni][2] * ib; v.y = o[ni][3] * ib;
        *(float2*)(yb + c) = v;
    }
}

// ---------------------------------------------------------------------------
extern "C" void kernel_launch(void* const* d_in, const int* in_sizes, int n_in,
                              void* d_out, int out_size) {
    const float* x    = (const float*)d_in[0];   // [B,T,C]
    const float* Wqkv = (const float*)d_in[1];   // [C,3C]
    const float* Wo   = (const float*)d_in[2];   // [C,C]
    const float* bo   = (const float*)d_in[3];   // [C]
    float* out = (float*)d_out;                  // [B,T,C]

    static bool attr_done = false;
    if (!attr_done) {
        cudaFuncSetAttribute(gemm_mma, cudaFuncAttributeMaxDynamicSharedMemorySize,
                             GEMM_SMEM);
        cudaFuncSetAttribute(flash_mma, cudaFuncAttributeMaxDynamicSharedMemorySize,
                             FLASH_SMEM);
        attr_done = true;
    }

    float* wqkv_t; cudaGetSymbolAddress((void**)&wqkv_t, g_wqkv_t);
    float* wo_t;   cudaGetSymbolAddress((void**)&wo_t,   g_wo_t);
    float* yptr;   cudaGetSymbolAddress((void**)&yptr,   g_y);

    // Transpose weights -> K-major B operands
    transpose_k<<<dim3(N_QKV / 32, Cq / 32), dim3(32, 8)>>>(Wqkv, wqkv_t, Cq, N_QKV);
    transpose_k<<<dim3(Cq / 32, Cq / 32), dim3(32, 8)>>>(Wo, wo_t, Cq, Cq);

    // QKV projection (tf32 mma.sync)
    gemm_mma<<<dim3(N_QKV / 128, Mrows / 128), 256, GEMM_SMEM>>>(
        x, wqkv_t, Cq, 0, nullptr, nullptr);

    // Attention (tf32 mma.sync flash)
    flash_mma<<<dim3(Tq / 128, Bq * Hq), 256, FLASH_SMEM>>>();

    // Output projection (tf32 mma.sync)
    gemm_mma<<<dim3(Cq / 128, Mrows / 128), 256, GEMM_SMEM>>>(
        yptr, wo_t, Cq, 1, bo, out);
}